// round 5
// baseline (speedup 1.0000x reference)
#include <cuda_runtime.h>
#include <cstdint>

#define NF 32
#define NPOLY 6545
#define BATCH 8192
#define ROWS_PER_BLOCK 32
#define NWARP 8
#define THREADS (32 * NWARP)
#define NGROUP 8                      /* feature groups (blocks along feature dim) */
#define NCHUNKS (NGROUP * NWARP)      /* 64 balanced warp-chunks */
#define TILE_P 16                     /* W rows per smem tile */
#define XS_BYTES (32 * 33 * 4)                      /* 4224  */
#define WBUF_BYTES (NWARP * 2 * TILE_P * NF * 4)    /* 32768 */
#define SMEM_BYTES (XS_BYTES + WBUF_BYTES)          /* 36992 */
#define NBLOCKS (256 * NGROUP)                      /* 2048 */

// scratch partials: [block][32 rows][32 cols]
__device__ float g_scratch[NBLOCKS * 1024];
// chunk boundaries: (f, a, b, p). f=-2 => const+linear item, f=-1 => quadratic
__device__ int4 g_bound[NCHUNKS + 1];

// ---------- PTX helpers ----------
__device__ __forceinline__ void cp16(uint32_t dst, const float* src) {
    unsigned long long g;
    asm volatile("cvta.to.global.u64 %0, %1;" : "=l"(g) : "l"(src));
    asm volatile("cp.async.cg.shared.global [%0], [%1], 16;" :: "r"(dst), "l"(g));
}
__device__ __forceinline__ void cp_commit() {
    asm volatile("cp.async.commit_group;" ::: "memory");
}
__device__ __forceinline__ void cp_wait0() {
    asm volatile("cp.async.wait_group 0;" ::: "memory");
}
__device__ __forceinline__ unsigned long long pack2(float f) {
    unsigned long long r;
    asm("mov.b64 %0, {%1, %1};" : "=l"(r) : "f"(f));
    return r;
}
#define FMA2(a, w, f) asm("fma.rn.f32x2 %0, %1, %2, %0;" : "+l"(a) : "l"(w), "l"(f))

// ---------- kernel 0: compute balanced chunk boundaries ----------
__global__ void setup_bounds() {
    int k = threadIdx.x;
    if (k > NCHUNKS) return;
    int T = (int)(((long long)NPOLY * k) / NCHUNKS);   // target monomial index
    if (k == NCHUNKS) { g_bound[k] = make_int4(32, 0, 0, NPOLY); return; }
    if (T < 33) { g_bound[k] = make_int4(-2, 0, T, T); return; }
    int cum = 33;
    for (int a = 0; a < NF; a++) {                      // quadratic items
        if (T < cum + a + 1) { g_bound[k] = make_int4(-1, a, T - cum, T); return; }
        cum += a + 1;
    }
    for (int f = 0; f < NF; f++)                        // cubic items
        for (int a = 0; a <= f; a++) {
            if (T < cum + a + 1) { g_bound[k] = make_int4(f, a, T - cum, T); return; }
            cum += a + 1;
        }
}

// Load one 16-row x 32-col fp32 W tile (2 KB) into smem, warp-cooperative.
__device__ __forceinline__ void load_tile(uint32_t dsts, const float* __restrict__ W,
                                          int row0, int lane) {
#pragma unroll
    for (int i = 0; i < 4; i++) {
        int e = i * 32 + lane;               // 16-byte unit index 0..127
        int r = row0 + (e >> 3);
        if (r > NPOLY - 1) r = NPOLY - 1;    // clamp (never consumed)
        cp16(dsts + (uint32_t)e * 16u, W + (size_t)r * NF + (e & 7) * 4);
    }
    cp_commit();
}

#define STEP(FEAT)                                                              \
    do {                                                                        \
        if ((tc & (TILE_P - 1)) == 0) {                                         \
            cp_wait0();                                                         \
            __syncwarp();                                                       \
            wcur = parity ? bufB : bufA;                                        \
            if (next_row < pend) {                                              \
                load_tile(parity ? sA : sB, W, next_row, lane);                 \
                next_row += TILE_P;                                             \
            }                                                                   \
            parity ^= 1;                                                        \
        }                                                                       \
        {                                                                       \
            const ulonglong2* wr =                                              \
                (const ulonglong2*)(wcur + (tc & (TILE_P - 1)) * (NF * 4));     \
            unsigned long long f2_ = pack2(FEAT);                               \
            ulonglong2 q0 = wr[0], q1 = wr[1], q2 = wr[2], q3 = wr[3];          \
            ulonglong2 q4 = wr[4], q5 = wr[5], q6 = wr[6], q7 = wr[7];          \
            FMA2(acc[0],  q0.x, f2_); FMA2(acc[1],  q0.y, f2_);                 \
            FMA2(acc[2],  q1.x, f2_); FMA2(acc[3],  q1.y, f2_);                 \
            FMA2(acc[4],  q2.x, f2_); FMA2(acc[5],  q2.y, f2_);                 \
            FMA2(acc[6],  q3.x, f2_); FMA2(acc[7],  q3.y, f2_);                 \
            FMA2(acc[8],  q4.x, f2_); FMA2(acc[9],  q4.y, f2_);                 \
            FMA2(acc[10], q5.x, f2_); FMA2(acc[11], q5.y, f2_);                 \
            FMA2(acc[12], q6.x, f2_); FMA2(acc[13], q6.y, f2_);                 \
            FMA2(acc[14], q7.x, f2_); FMA2(acc[15], q7.y, f2_);                 \
            tc++;                                                               \
        }                                                                       \
    } while (0)

// ---------- kernel 1: partial products ----------
__global__ void __launch_bounds__(THREADS, 4)
taylor_partial(const float* __restrict__ x, const float* __restrict__ W) {
    extern __shared__ char smem[];
    float* xs = (float*)smem;             // [32][33] padded
    char* wbase = smem + XS_BYTES;        // 8 warps x 2 x 2KB double buffers

    const int tid  = threadIdx.x;
    const int lane = tid & 31;            // lane == row within tile
    const int w    = tid >> 5;
    const int rt   = blockIdx.x >> 3;     // row tile
    const int gid  = blockIdx.x & (NGROUP - 1);
    const int row0 = rt * ROWS_PER_BLOCK;

    for (int idx = tid; idx < 32 * 32; idx += THREADS) {
        int r = idx >> 5, c = idx & 31;
        xs[r * 33 + c] = x[(size_t)(row0 + r) * NF + c];
    }
    __syncthreads();

    const float* myx = xs + lane * 33;

    const int chunk = gid * NWARP + w;
    const int4 b0v = g_bound[chunk];
    const int4 b1v = g_bound[chunk + 1];
    int f = b0v.x, a = b0v.y, b = b0v.z;
    const int pstart = b0v.w;
    const int pend = b1v.w;
    int rem = pend - pstart;

    char* bufA = wbase + w * (2 * TILE_P * NF * 4);
    char* bufB = bufA + TILE_P * NF * 4;
    const uint32_t sA = (uint32_t)__cvta_generic_to_shared(bufA);
    const uint32_t sB = (uint32_t)__cvta_generic_to_shared(bufB);

    load_tile(sA, W, pstart, lane);
    int next_row = pstart + TILE_P;
    int parity = 0;
    const char* wcur = bufA;
    int tc = 0;

    unsigned long long acc[16];
#pragma unroll
    for (int i = 0; i < 16; i++) acc[i] = 0ULL;

    // walk the monomial items starting mid-stream at (f, a, b)
    while (rem > 0) {
        if (f == -2) {                       // const + linear item (33 feats)
            int cnt = 33 - b; if (cnt > rem) cnt = rem;
            for (int i = 0; i < cnt; i++) {
                int bb = b + i;
                STEP(bb == 0 ? 1.0f : myx[bb - 1]);
            }
            rem -= cnt; b += cnt;
            if (b >= 33) { f = -1; a = 0; b = 0; }
        } else if (f == -1) {                // quadratic item a: feats x_a*x_b, b<=a
            int cnt = (a + 1) - b; if (cnt > rem) cnt = rem;
            float xa = myx[a];
            for (int i = 0; i < cnt; i++) STEP(xa * myx[b + i]);
            rem -= cnt; b += cnt;
            if (b > a) { b = 0; a++; if (a >= NF) { f = 0; a = 0; } }
        } else {                             // cubic item (f,a): t*x_b, b<=a
            int cnt = (a + 1) - b; if (cnt > rem) cnt = rem;
            float t = myx[f] * myx[a];
            for (int i = 0; i < cnt; i++) STEP(t * myx[b + i]);
            rem -= cnt; b += cnt;
            if (b > a) { b = 0; a++; if (a > f) { f++; a = 0; } }
        }
    }

    cp_wait0();
    __syncthreads();

    // per-warp partials -> smem overlay (whole smem region), padded [8][32][33]
    float* red = (float*)smem;
#pragma unroll
    for (int i = 0; i < 16; i++) {
        float lo, hi;
        asm("mov.b64 {%0, %1}, %2;" : "=f"(lo), "=f"(hi) : "l"(acc[i]));
        red[(w * 32 + lane) * 33 + 2 * i]     = lo;
        red[(w * 32 + lane) * 33 + 2 * i + 1] = hi;
    }
    __syncthreads();

    // reduce 8 warps -> block partial in scratch (float4 per thread)
    {
        int idx = tid * 4;                   // 0..1020
        int r = idx >> 5, c = idx & 31;
        float4 s;
        s.x = 0.f; s.y = 0.f; s.z = 0.f; s.w = 0.f;
#pragma unroll
        for (int k = 0; k < NWARP; k++) {
            const float* rr = red + (k * 32 + r) * 33 + c;
            s.x += rr[0]; s.y += rr[1]; s.z += rr[2]; s.w += rr[3];
        }
        *(float4*)(g_scratch + (size_t)blockIdx.x * 1024 + idx) = s;
    }
}

// ---------- kernel 2: residual + reduce groups ----------
__global__ void __launch_bounds__(256)
taylor_final(const float* __restrict__ x, float* __restrict__ out) {
    int idx = (blockIdx.x * 256 + threadIdx.x) * 4;     // element index
    int row = idx >> 5;
    int rt = row >> 5;
    int inner = (row & 31) * 32 + (idx & 31);
    float4 v = *(const float4*)(x + idx);
#pragma unroll
    for (int g = 0; g < NGROUP; g++) {
        const float4 t = *(const float4*)(g_scratch +
                           ((size_t)(rt * NGROUP + g) * 1024) + inner);
        v.x += t.x; v.y += t.y; v.z += t.z; v.w += t.w;
    }
    *(float4*)(out + idx) = v;
}

extern "C" void kernel_launch(void* const* d_in, const int* in_sizes, int n_in,
                              void* d_out, int out_size) {
    const float* x = (const float*)d_in[0];
    const float* W = (const float*)d_in[1];
    if (n_in >= 2 && in_sizes[0] == NPOLY * NF && in_sizes[1] == BATCH * NF) {
        const float* t = x; x = W; W = t;
    }
    cudaFuncSetAttribute(taylor_partial,
                         cudaFuncAttributeMaxDynamicSharedMemorySize, SMEM_BYTES);
    setup_bounds<<<1, 128>>>();
    taylor_partial<<<NBLOCKS, THREADS, SMEM_BYTES>>>(x, W);
    taylor_final<<<(BATCH * NF) / (256 * 4), 256>>>(x, (float*)d_out);
}

// round 8
// speedup vs baseline: 1.5447x; 1.5447x over previous
#include <cuda_runtime.h>
#include <cstdint>

#define NF 32
#define NPOLY 6545
#define BATCH 8192
#define NWARP 8
#define THREADS 256
#define NGROUP 8                      /* feature groups (blocks per row-tile) */
#define NCHUNKS (NGROUP * NWARP)      /* 64 balanced warp-chunks */
#define TILE_P 16                     /* W rows per smem tile */
#define WROW_BYTES (NF * 4)
#define XS_BYTES (32 * 33 * 4)                        /* 4224  */
#define WBUF_BYTES (NWARP * 2 * TILE_P * WROW_BYTES)  /* 32768 */
#define SMEM_BYTES (XS_BYTES + WBUF_BYTES)            /* 36992 */
#define NBLOCKS (256 * NGROUP)                        /* 2048 */

// scratch partials: [block][32 rows][32 cols]
__device__ float g_scratch[NBLOCKS * 1024];
// per-row-tile completion counters (wrap-reset by atomicInc, zero-init)
__device__ unsigned int g_cnt[256];

// ---------- PTX helpers ----------
__device__ __forceinline__ void cp16(uint32_t dst, const float* src) {
    unsigned long long g;
    asm volatile("cvta.to.global.u64 %0, %1;" : "=l"(g) : "l"(src));
    asm volatile("cp.async.cg.shared.global [%0], [%1], 16;" :: "r"(dst), "l"(g));
}
__device__ __forceinline__ void cp_commit() {
    asm volatile("cp.async.commit_group;" ::: "memory");
}
__device__ __forceinline__ void cp_wait0() {
    asm volatile("cp.async.wait_group 0;" ::: "memory");
}
__device__ __forceinline__ unsigned long long pack2(float f) {
    unsigned long long r;
    asm("mov.b64 %0, {%1, %1};" : "=l"(r) : "f"(f));
    return r;
}
#define FMA2(a, w, f) asm("fma.rn.f32x2 %0, %1, %2, %0;" : "+l"(a) : "l"(w), "l"(f))

// Decode monomial index T -> walker state (f,a,b).
// f=-2: const+linear segment (b = position 0..32). f=-1: quadratic item a,
// offset b. f>=0: cubic item (f,a), offset b.
__device__ __forceinline__ void decode_T(int T, int& f, int& a, int& b) {
    if (T < 33) { f = -2; a = 0; b = T; return; }
    if (T < 561) {
        int r = T - 33;
        int aa = 0;
        while ((aa + 1) * (aa + 2) / 2 <= r) aa++;
        f = -1; a = aa; b = r - aa * (aa + 1) / 2; return;
    }
    int r = T - 561;
    int ff = 0;
    while ((ff + 1) * (ff + 2) * (ff + 3) / 6 <= r) ff++;
    r -= ff * (ff + 1) * (ff + 2) / 6;
    int aa = 0;
    while ((aa + 1) * (aa + 2) / 2 <= r) aa++;
    f = ff; a = aa; b = r - aa * (aa + 1) / 2;
}

// Load one 16-row x 32-col fp32 W tile (2 KB) into smem, warp-cooperative.
__device__ __forceinline__ void load_tile(uint32_t dsts, const float* __restrict__ W,
                                          int row0, int lane) {
#pragma unroll
    for (int i = 0; i < 4; i++) {
        int e = i * 32 + lane;               // 16-byte unit index 0..127
        int r = row0 + (e >> 3);
        if (r > NPOLY - 1) r = NPOLY - 1;    // clamp (never consumed)
        cp16(dsts + (uint32_t)e * 16u, W + (size_t)r * NF + (e & 7) * 4);
    }
    cp_commit();
}

// One feature step. Thread covers 2 rows x 16 cols: V0 feeds rows 2*rg,
// V1 feeds 2*rg+1. 4x LDS.128 of W (64B chunk per col-half) + 16 FMA2.
#define STEP(V0, V1)                                                            \
    do {                                                                        \
        if ((tc & (TILE_P - 1)) == 0) {                                         \
            cp_wait0();                                                         \
            __syncwarp();                                                       \
            wcur = parity ? bufB : bufA;                                        \
            if (next_row < pend) {                                              \
                load_tile(parity ? sA : sB, W, next_row, lane);                 \
                next_row += TILE_P;                                             \
            }                                                                   \
            parity ^= 1;                                                        \
        }                                                                       \
        {                                                                       \
            const ulonglong2* wr = (const ulonglong2*)                          \
                (wcur + (tc & (TILE_P - 1)) * WROW_BYTES + cg * 64);            \
            unsigned long long f20 = pack2(V0);                                 \
            unsigned long long f21 = pack2(V1);                                 \
            ulonglong2 q0 = wr[0], q1 = wr[1], q2 = wr[2], q3 = wr[3];          \
            FMA2(acc[0], q0.x, f20); FMA2(acc[1], q0.y, f20);                   \
            FMA2(acc[2], q1.x, f20); FMA2(acc[3], q1.y, f20);                   \
            FMA2(acc[4], q2.x, f20); FMA2(acc[5], q2.y, f20);                   \
            FMA2(acc[6], q3.x, f20); FMA2(acc[7], q3.y, f20);                   \
            FMA2(acc[8],  q0.x, f21); FMA2(acc[9],  q0.y, f21);                 \
            FMA2(acc[10], q1.x, f21); FMA2(acc[11], q1.y, f21);                 \
            FMA2(acc[12], q2.x, f21); FMA2(acc[13], q2.y, f21);                 \
            FMA2(acc[14], q3.x, f21); FMA2(acc[15], q3.y, f21);                 \
            tc++;                                                               \
        }                                                                       \
    } while (0)

__global__ void __launch_bounds__(THREADS, 3)
taylor_fused(const float* __restrict__ x, const float* __restrict__ W,
             float* __restrict__ out) {
    extern __shared__ char smem[];
    __shared__ int s_last;
    float* xs = (float*)smem;             // [32][33] padded
    char* wbase = smem + XS_BYTES;        // 8 warps x 2 x 2KB double buffers

    const int tid  = threadIdx.x;
    const int lane = tid & 31;
    const int w    = tid >> 5;
    const int rt   = blockIdx.x >> 3;     // row tile (0..255)
    const int gid  = blockIdx.x & (NGROUP - 1);
    const int row0 = rt * 32;

    // thread tile: 2 rows x 16 cols
    const int rg = lane & 15;             // row pair index (rows 2rg, 2rg+1)
    const int cg = lane >> 4;             // col half (0 or 1)

    // stage x tile (coalesced), padded stride 33
    for (int idx = tid; idx < 32 * 32; idx += THREADS) {
        int r = idx >> 5, c = idx & 31;
        xs[r * 33 + c] = x[(size_t)(row0 + r) * NF + c];
    }
    __syncthreads();

    const float* myx0 = xs + (2 * rg) * 33;
    const float* myx1 = myx0 + 33;

    // this warp's monomial range [pstart, pend), decoded in-warp
    const int chunk = gid * NWARP + w;
    const int pstart = (int)(((long long)NPOLY * chunk) / NCHUNKS);
    const int pend   = (int)(((long long)NPOLY * (chunk + 1)) / NCHUNKS);
    int f, a, b;
    decode_T(pstart, f, a, b);
    int rem = pend - pstart;

    char* bufA = wbase + w * (2 * TILE_P * WROW_BYTES);
    char* bufB = bufA + TILE_P * WROW_BYTES;
    const uint32_t sA = (uint32_t)__cvta_generic_to_shared(bufA);
    const uint32_t sB = (uint32_t)__cvta_generic_to_shared(bufB);

    load_tile(sA, W, pstart, lane);
    int next_row = pstart + TILE_P;
    int parity = 0;
    const char* wcur = bufA;
    int tc = 0;

    unsigned long long acc[16];
#pragma unroll
    for (int i = 0; i < 16; i++) acc[i] = 0ULL;

    // walk the monomial items starting mid-stream at (f, a, b)
    while (rem > 0) {
        if (f == -2) {                       // const + linear (33 feats)
            int cnt = 33 - b; if (cnt > rem) cnt = rem;
            for (int i = 0; i < cnt; i++) {
                int bb = b + i;
                float v0 = (bb == 0) ? 1.0f : myx0[bb - 1];
                float v1 = (bb == 0) ? 1.0f : myx1[bb - 1];
                STEP(v0, v1);
            }
            rem -= cnt; b += cnt;
            if (b >= 33) { f = -1; a = 0; b = 0; }
        } else if (f == -1) {                // quadratic item a: x_a*x_b, b<=a
            int cnt = (a + 1) - b; if (cnt > rem) cnt = rem;
            float t0 = myx0[a], t1 = myx1[a];
            for (int i = 0; i < cnt; i++) STEP(t0 * myx0[b + i], t1 * myx1[b + i]);
            rem -= cnt; b += cnt;
            if (b > a) { b = 0; a++; if (a >= NF) { f = 0; a = 0; } }
        } else {                             // cubic item (f,a): x_f*x_a*x_b, b<=a
            int cnt = (a + 1) - b; if (cnt > rem) cnt = rem;
            float t0 = myx0[f] * myx0[a], t1 = myx1[f] * myx1[a];
            for (int i = 0; i < cnt; i++) STEP(t0 * myx0[b + i], t1 * myx1[b + i]);
            rem -= cnt; b += cnt;
            if (b > a) { b = 0; a++; if (a > f) { f++; a = 0; } }
        }
    }

    cp_wait0();          // drain in-flight prefetch before smem overlay
    __syncthreads();

    // per-warp partials -> smem overlay, padded [8][32][33]
    float* red = (float*)smem;
    {
        float* rr0 = red + (w * 32 + 2 * rg) * 33 + 16 * cg;
        float* rr1 = rr0 + 33;
#pragma unroll
        for (int i = 0; i < 8; i++) {
            float lo, hi;
            asm("mov.b64 {%0, %1}, %2;" : "=f"(lo), "=f"(hi) : "l"(acc[i]));
            rr0[2 * i] = lo; rr0[2 * i + 1] = hi;
            asm("mov.b64 {%0, %1}, %2;" : "=f"(lo), "=f"(hi) : "l"(acc[8 + i]));
            rr1[2 * i] = lo; rr1[2 * i + 1] = hi;
        }
    }
    __syncthreads();

    // reduce 8 warps -> block partial in scratch (float4 per thread)
    const int idx4 = tid * 4;                // 0..1020
    {
        int r = idx4 >> 5, c = idx4 & 31;
        float4 s; s.x = 0.f; s.y = 0.f; s.z = 0.f; s.w = 0.f;
#pragma unroll
        for (int k = 0; k < NWARP; k++) {
            const float* rr = red + (k * 32 + r) * 33 + c;
            s.x += rr[0]; s.y += rr[1]; s.z += rr[2]; s.w += rr[3];
        }
        *(float4*)(g_scratch + (size_t)blockIdx.x * 1024 + idx4) = s;
    }

    // last block of this row-tile finishes: out = x + sum(groups)
    __threadfence();
    __syncthreads();
    if (tid == 0) {
        unsigned int old = atomicInc(&g_cnt[rt], NGROUP - 1);  // wraps 7 -> 0
        s_last = (old == NGROUP - 1);
    }
    __syncthreads();
    if (s_last) {
        size_t base = (size_t)rt * 1024 + idx4;   // x/out flat index
        float4 v = *(const float4*)(x + base);
#pragma unroll
        for (int g = 0; g < NGROUP; g++) {
            float4 t = __ldcg((const float4*)(g_scratch +
                              ((size_t)(rt * NGROUP + g) * 1024) + idx4));
            v.x += t.x; v.y += t.y; v.z += t.z; v.w += t.w;
        }
        *(float4*)(out + base) = v;
    }
}

extern "C" void kernel_launch(void* const* d_in, const int* in_sizes, int n_in,
                              void* d_out, int out_size) {
    const float* x = (const float*)d_in[0];
    const float* W = (const float*)d_in[1];
    if (n_in >= 2 && in_sizes[0] == NPOLY * NF && in_sizes[1] == BATCH * NF) {
        const float* t = x; x = W; W = t;
    }
    taylor_fused<<<NBLOCKS, THREADS, SMEM_BYTES>>>(x, W, (float*)d_out);
}